// round 6
// baseline (speedup 1.0000x reference)
#include <cuda_runtime.h>
#include <cstdint>

#define Bb   4
#define NN   2048
#define FIN  256
#define FOUT 128
#define HH   4
#define NEG  0.2f
#define TK   32
#define NT   (NN / TK)   // 64

// ---------------------------------------------------------------------------
// scratch (no cudaMalloc allowed)
// ---------------------------------------------------------------------------
__device__ float    g_Wh[Bb * NN * FOUT];        // [b][n][o]  4 MB
__device__ float2   g_iAC[Bb * HH * NN];         // (e^el, e^.2el) per (b,h,i)
__device__ float2   g_jEFi[Bb * NN * HH];        // (e^er, e^.2er), [(b*NN+n)*4+h]
__device__ float2   g_irow[Bb * HH * NN];        // prescaled (A*0.25/Z, C*0.25/Z)
__device__ uint32_t g_adjbits[NN * 64];          // 512 KB
__device__ uint4    g_Bfrag4[Bb * NT * 1024];    // Wh B-fragments (tf32), paired

// ---------------------------------------------------------------------------
__device__ __forceinline__ uint32_t f2tf32(float f) {
    uint32_t u;
    asm("cvt.rna.tf32.f32 %0, %1;" : "=r"(u) : "f"(f));
    return u;
}
__device__ __forceinline__ void mma_tf32(float& c0, float& c1, float& c2, float& c3,
                                         uint32_t a0, uint32_t a1, uint32_t a2, uint32_t a3,
                                         uint32_t b0, uint32_t b1) {
    asm volatile("mma.sync.aligned.m16n8k8.row.col.f32.tf32.tf32.f32 "
                 "{%0,%1,%2,%3}, {%4,%5,%6,%7}, {%8,%9}, {%0,%1,%2,%3};"
                 : "+f"(c0), "+f"(c1), "+f"(c2), "+f"(c3)
                 : "r"(a0), "r"(a1), "r"(a2), "r"(a3), "r"(b0), "r"(b1));
}
__device__ __forceinline__ void cp_async16(uint32_t dst, const void* src) {
    asm volatile("cp.async.cg.shared.global [%0], [%1], 16;" :: "r"(dst), "l"(src));
}
#define CP_COMMIT() asm volatile("cp.async.commit_group;" ::: "memory")
#define CP_WAIT0()  asm volatile("cp.async.wait_group 0;" ::: "memory")

// ---------------------------------------------------------------------------
// Kernel 0: adj -> bitmask
// ---------------------------------------------------------------------------
__global__ __launch_bounds__(64) void adjbits_kernel(const int* __restrict__ adj)
{
    const int row = blockIdx.x, w = threadIdx.x;
    const int4* p = (const int4*)(adj + (size_t)row * NN + w * 32);
    uint32_t bits = 0;
#pragma unroll
    for (int q = 0; q < 8; q++) {
        int4 v = __ldg(p + q);
        bits |= (v.x ? 1u : 0u) << (q * 4 + 0);
        bits |= (v.y ? 1u : 0u) << (q * 4 + 1);
        bits |= (v.z ? 1u : 0u) << (q * 4 + 2);
        bits |= (v.w ? 1u : 0u) << (q * 4 + 3);
    }
    g_adjbits[row * 64 + w] = bits;
}

// ---------------------------------------------------------------------------
// Kernel 1: Wh = h @ W^T + b  (register-tiled fp32 GEMM)
// ---------------------------------------------------------------------------
__global__ __launch_bounds__(256) void wh2_kernel(const float* __restrict__ h,
                                                  const float* __restrict__ Ww,
                                                  const float* __restrict__ Wb)
{
    __shared__ float As[32][32];
    __shared__ float Bs[32][128];
    const int t     = threadIdx.x;
    const int grow0 = blockIdx.x * 32;
    const int col   = (t & 31) * 4;
    const int row0  = (t >> 5) * 4;

    float acc[4][4];
#pragma unroll
    for (int r = 0; r < 4; r++)
#pragma unroll
        for (int c = 0; c < 4; c++) acc[r][c] = 0.f;

    for (int kb = 0; kb < FIN; kb += 32) {
        {
            int r = t >> 3, k4 = (t & 7) * 4;
            *(float4*)&As[r][k4] =
                *(const float4*)(h + (size_t)(grow0 + r) * FIN + kb + k4);
        }
        {
            int o = t >> 1, kh = (t & 1) * 16;
#pragma unroll
            for (int s2 = 0; s2 < 4; s2++) {
                float4 v = *(const float4*)(Ww + (size_t)o * FIN + kb + kh + s2 * 4);
                Bs[kh + s2 * 4 + 0][o] = v.x;
                Bs[kh + s2 * 4 + 1][o] = v.y;
                Bs[kh + s2 * 4 + 2][o] = v.z;
                Bs[kh + s2 * 4 + 3][o] = v.w;
            }
        }
        __syncthreads();
#pragma unroll
        for (int k = 0; k < 32; k++) {
            float4 bv = *(const float4*)&Bs[k][col];
            float a0 = As[row0 + 0][k], a1 = As[row0 + 1][k];
            float a2 = As[row0 + 2][k], a3 = As[row0 + 3][k];
            acc[0][0] += a0 * bv.x; acc[0][1] += a0 * bv.y; acc[0][2] += a0 * bv.z; acc[0][3] += a0 * bv.w;
            acc[1][0] += a1 * bv.x; acc[1][1] += a1 * bv.y; acc[1][2] += a1 * bv.z; acc[1][3] += a1 * bv.w;
            acc[2][0] += a2 * bv.x; acc[2][1] += a2 * bv.y; acc[2][2] += a2 * bv.z; acc[2][3] += a2 * bv.w;
            acc[3][0] += a3 * bv.x; acc[3][1] += a3 * bv.y; acc[3][2] += a3 * bv.z; acc[3][3] += a3 * bv.w;
        }
        __syncthreads();
    }

    float4 bias = *(const float4*)(Wb + col);
    const float bc[4] = {bias.x, bias.y, bias.z, bias.w};
#pragma unroll
    for (int r = 0; r < 4; r++) {
        float4 o4 = make_float4(acc[r][0] + bc[0], acc[r][1] + bc[1],
                                acc[r][2] + bc[2], acc[r][3] + bc[3]);
        *(float4*)(g_Wh + (size_t)(grow0 + row0 + r) * FOUT + col) = o4;
    }
}

// ---------------------------------------------------------------------------
// Kernel 2: per (b,h,n): el/er dot products + exps (exact fp32)
// ---------------------------------------------------------------------------
__global__ __launch_bounds__(256) void pack_kernel(const float* __restrict__ attn_w)
{
    const int t    = threadIdx.x;
    const int warp = t >> 5;
    const int lane = t & 31;
    const int row  = blockIdx.x * 8 + warp;
    const int b    = row >> 11;
    const int n    = row & (NN - 1);

    float4 wh = *(const float4*)(g_Wh + (size_t)row * FOUT + lane * 4);
#pragma unroll
    for (int hh = 0; hh < HH; hh++) {
        float4 al = *(const float4*)(attn_w + hh * 2 * FOUT + lane * 4);
        float4 ar = *(const float4*)(attn_w + hh * 2 * FOUT + FOUT + lane * 4);
        float sl = wh.x * al.x + wh.y * al.y + wh.z * al.z + wh.w * al.w;
        float sr = wh.x * ar.x + wh.y * ar.y + wh.z * ar.z + wh.w * ar.w;
#pragma unroll
        for (int off = 16; off > 0; off >>= 1) {
            sl += __shfl_xor_sync(0xffffffffu, sl, off);
            sr += __shfl_xor_sync(0xffffffffu, sr, off);
        }
        if (lane == 0) {
            g_iAC[(b * HH + hh) * NN + n]            = make_float2(expf(sl), expf(NEG * sl));
            g_jEFi[((size_t)(b * NN + n)) * HH + hh] = make_float2(expf(sr), expf(NEG * sr));
        }
    }
}

// ---------------------------------------------------------------------------
// Kernel 3: repack Wh into paired B-fragments (tf32). (unchanged layout)
// ---------------------------------------------------------------------------
__global__ __launch_bounds__(256) void bfrag_kernel()
{
    const int jt = blockIdx.x, b = blockIdx.y, t = threadIdx.x;
    const size_t base = ((size_t)b * NT + jt) * 1024;
#pragma unroll
    for (int q = 0; q < 4; q++) {
        const int s    = q * 256 + t;
        const int lane = s & 31;
        const int ntp  = (s >> 5) & 7;
        const int ks   = s >> 8;
        const int j    = jt * TK + ks * 8 + (lane & 3);
        const int o0   = (ntp * 2) * 8 + (lane >> 2);
        const int o1   = o0 + 8;
        float x = __ldg(&g_Wh[((size_t)(b * NN + j))     * FOUT + o0]);
        float y = __ldg(&g_Wh[((size_t)(b * NN + j + 4)) * FOUT + o0]);
        float z = __ldg(&g_Wh[((size_t)(b * NN + j))     * FOUT + o1]);
        float w = __ldg(&g_Wh[((size_t)(b * NN + j + 4)) * FOUT + o1]);
        g_Bfrag4[base + s] = make_uint4(f2tf32(x), f2tf32(y), f2tf32(z), f2tf32(w));
    }
}

// ---------------------------------------------------------------------------
// Kernel 4: Z pre-pass. Z_h[i] = sum_j mask * max(A_h E_hj, C_h F_hj);
// writes g_irow = (A*0.25/Z, C*0.25/Z) (0 if Z==0).
// grid (64, 4), 256 thr: 32 rows/CTA, thread = (i = t>>3, jq = t&7).
// ---------------------------------------------------------------------------
__global__ __launch_bounds__(256) void zsum_kernel()
{
    __shared__ float zr[32][4][8];
    const int t  = threadIdx.x;
    const int b  = blockIdx.y;
    const int i0 = blockIdx.x * 32;
    const int i  = t >> 3, jq = t & 7;
    const int gi = i0 + i;

    float2 AC[4];
#pragma unroll
    for (int h = 0; h < HH; h++) AC[h] = __ldg(&g_iAC[(b * HH + h) * NN + gi]);

    float z0 = 0.f, z1 = 0.f, z2 = 0.f, z3 = 0.f;
    const float4*   src  = (const float4*)(g_jEFi + (size_t)b * NN * HH);
    const uint32_t* mrow = g_adjbits + (size_t)gi * 64;

    for (int jt = 0; jt < NT; jt++) {
        const uint32_t mw = __ldg(mrow + jt);
#pragma unroll
        for (int e = 0; e < 4; e++) {
            const int j = jt * TK + jq * 4 + e;
            float4 q01 = __ldg(src + j * 2);
            float4 q23 = __ldg(src + j * 2 + 1);
            if ((mw >> (jq * 4 + e)) & 1u) {
                z0 += fmaxf(AC[0].x * q01.x, AC[0].y * q01.y);
                z1 += fmaxf(AC[1].x * q01.z, AC[1].y * q01.w);
                z2 += fmaxf(AC[2].x * q23.x, AC[2].y * q23.y);
                z3 += fmaxf(AC[3].x * q23.z, AC[3].y * q23.w);
            }
        }
    }
    zr[i][0][jq] = z0; zr[i][1][jq] = z1; zr[i][2][jq] = z2; zr[i][3][jq] = z3;
    __syncthreads();

    if (t < 128) {
        const int ii = t >> 2, h = t & 3;
        float Z = 0.f;
#pragma unroll
        for (int g = 0; g < 8; g++) Z += zr[ii][h][g];
        float2 ac  = __ldg(&g_iAC[(b * HH + h) * NN + i0 + ii]);
        float  inv = (Z > 0.f) ? 0.25f / Z : 0.f;
        g_irow[(b * HH + h) * NN + i0 + ii] = make_float2(ac.x * inv, ac.y * inv);
    }
}

// ---------------------------------------------------------------------------
// Kernel 5 (main): P_avg @ Wh via mma.sync tf32.
// Block = (b, 64 i-rows); M=64 (4 m16 tiles), heads pre-averaged. grid (32,4).
// 8 warps: consume 2x4 (mw rows32, nw cols32); A-gen: amt = w&3, ks pair = w>>2.
// ---------------------------------------------------------------------------
// SMEM: Af[2][4mt][4ks][32] uint4 (16K) @0 | Bf[2][4ks][8ntp][32] uint4 (32K) @16384
//     | JP[2][64] float4 (2K) @49152
#define SM_A(p, mt, ks, ln)   ((((p) * 4 + (mt)) * 4 + (ks)) * 32 + (ln))
#define SM_B4(p, ks, ntp, ln) ((((p) * 4 + (ks)) * 8 + (ntp)) * 32 + (ln))
#define OFF_BF 16384
#define OFF_JP 49152
#define SMEM_BYTES 51200

__global__ __launch_bounds__(256, 2) void gat_main_mma(float* __restrict__ out)
{
    extern __shared__ char smem[];
    uint4*  Af  = (uint4*)smem;
    uint4*  Bf  = (uint4*)(smem + OFF_BF);
    float4* JPf = (float4*)(smem + OFF_JP);
    const uint32_t Bf_sa = (uint32_t)__cvta_generic_to_shared(Bf);
    const uint32_t JP_sa = (uint32_t)__cvta_generic_to_shared(JPf);

    const int t    = threadIdx.x;
    const int w    = t >> 5;
    const int lane = t & 31;
    const int mw   = w >> 2;            // consume: 0..1 (32 rows each)
    const int nw   = w & 3;             // consume: 0..3 (32 cols each)
    const int b    = blockIdx.y;
    const int i0   = blockIdx.x * 64;

    const int r   = lane >> 2;          // 0..7
    const int c   = lane & 3;           // 0..3
    const int amt = w & 3;              // A-gen m16 tile 0..3
    const int ks0 = (w >> 2) * 2;       // A-gen ks pair {ks0, ks0+1}

    const int gia = i0 + amt * 16 + r;  // generator rows (global)
    const int gib = gia + 8;

    float2 RA[4], RB[4];                // prescaled (A', C') per head
#pragma unroll
    for (int h = 0; h < HH; h++) {
        RA[h] = __ldg(&g_irow[(b * HH + h) * NN + gia]);
        RB[h] = __ldg(&g_irow[(b * HH + h) * NN + gib]);
    }
    const uint32_t* mba   = g_adjbits + (size_t)gia * 64;
    const uint32_t* mbb   = g_adjbits + (size_t)gib * 64;
    const uint4*    bbase = g_Bfrag4 + (size_t)b * NT * 1024;
    const float4*   jsrc  = (const float4*)(g_jEFi + (size_t)b * NN * HH);

    float acc[2][4][4];
#pragma unroll
    for (int a = 0; a < 2; a++)
#pragma unroll
        for (int n = 0; n < 4; n++)
#pragma unroll
            for (int k = 0; k < 4; k++) acc[a][n][k] = 0.f;

    auto stage = [&](int jn, int q) {
        const uint4* src = bbase + (size_t)jn * 1024;
        const uint32_t bdst = Bf_sa + (uint32_t)q * 16384u;
#pragma unroll
        for (int k4 = 0; k4 < 4; k4++)
            cp_async16(bdst + (uint32_t)(k4 * 256 + t) * 16u, src + k4 * 256 + t);
        if (t < 64)
            cp_async16(JP_sa + (uint32_t)(q * 64 + t) * 16u, jsrc + jn * 64 + t);
        CP_COMMIT();
    };

    auto agen = [&](int p, uint32_t ma, uint32_t mb2) {
        const float4* JP = JPf + p * 64;
#pragma unroll
        for (int kk = 0; kk < 2; kk++) {
            const int ks = ks0 + kk;
            const int jA = ks * 8 + c;
            float4 a01 = JP[jA * 2],       a23 = JP[jA * 2 + 1];
            float4 b01 = JP[(jA + 4) * 2], b23 = JP[(jA + 4) * 2 + 1];

            float vaA = (fmaxf(RA[0].x * a01.x, RA[0].y * a01.y)
                       + fmaxf(RA[1].x * a01.z, RA[1].y * a01.w))
                      + (fmaxf(RA[2].x * a23.x, RA[2].y * a23.y)
                       + fmaxf(RA[3].x * a23.z, RA[3].y * a23.w));
            float vbA = (fmaxf(RB[0].x * a01.x, RB[0].y * a01.y)
                       + fmaxf(RB[1].x * a01.z, RB[1].y * a01.w))
                      + (fmaxf(RB[2].x * a23.x, RB[2].y * a23.y)
                       + fmaxf(RB[3].x * a23.z, RB[3].y * a23.w));
            float vaB = (fmaxf(RA[0].x * b01.x, RA[0].y * b01.y)
                       + fmaxf(RA[1].x * b01.z, RA[1].y * b01.w))
                      + (fmaxf(RA[2].x * b23.x, RA[2].y * b23.y)
                       + fmaxf(RA[3].x * b23.z, RA[3].y * b23.w));
            float vbB = (fmaxf(RB[0].x * b01.x, RB[0].y * b01.y)
                       + fmaxf(RB[1].x * b01.z, RB[1].y * b01.w))
                      + (fmaxf(RB[2].x * b23.x, RB[2].y * b23.y)
                       + fmaxf(RB[3].x * b23.z, RB[3].y * b23.w));

            const int sh = ks * 8 + c;
            vaA = ((ma  >> sh)       & 1u) ? vaA : 0.f;
            vbA = ((mb2 >> sh)       & 1u) ? vbA : 0.f;
            vaB = ((ma  >> (sh + 4)) & 1u) ? vaB : 0.f;
            vbB = ((mb2 >> (sh + 4)) & 1u) ? vbB : 0.f;

            Af[SM_A(p, amt, ks, lane)] =
                make_uint4(f2tf32(vaA), f2tf32(vbA), f2tf32(vaB), f2tf32(vbB));
        }
    };

    auto consume = [&](int p) {
#pragma unroll
        for (int ks = 0; ks < 4; ks++) {
            uint4 a0 = Af[SM_A(p, mw * 2 + 0, ks, lane)];
            uint4 a1 = Af[SM_A(p, mw * 2 + 1, ks, lane)];
            uint4 b0 = Bf[SM_B4(p, ks, nw * 2 + 0, lane)];
            uint4 b1 = Bf[SM_B4(p, ks, nw * 2 + 1, lane)];
            mma_tf32(acc[0][0][0], acc[0][0][1], acc[0][0][2], acc[0][0][3],
                     a0.x, a0.y, a0.z, a0.w, b0.x, b0.y);
            mma_tf32(acc[0][1][0], acc[0][1][1], acc[0][1][2], acc[0][1][3],
                     a0.x, a0.y, a0.z, a0.w, b0.z, b0.w);
            mma_tf32(acc[0][2][0], acc[0][2][1], acc[0][2][2], acc[0][2][3],
                     a0.x, a0.y, a0.z, a0.w, b1.x, b1.y);
            mma_tf32(acc[0][3][0], acc[0][3][1], acc[0][3][2], acc[0][3][3],
                     a0.x, a0.y, a0.z, a0.w, b1.z, b1.w);
            mma_tf32(acc[1][0][0], acc[1][0][1], acc[1][0][2], acc[1][0][3],
                     a1.x, a1.y, a1.z, a1.w, b0.x, b0.y);
            mma_tf32(acc[1][1][0], acc[1][1][1], acc[1][1][2], acc[1][1][3],
                     a1.x, a1.y, a1.z, a1.w, b0.z, b0.w);
            mma_tf32(acc[1][2][0], acc[1][2][1], acc[1][2][2], acc[1][2][3],
                     a1.x, a1.y, a1.z, a1.w, b1.x, b1.y);
            mma_tf32(acc[1][3][0], acc[1][3][1], acc[1][3][2], acc[1][3][3],
                     a1.x, a1.y, a1.z, a1.w, b1.z, b1.w);
        }
    };

    // prologue
    stage(0, 0);
    uint32_t maC = __ldg(mba), mbC = __ldg(mbb);
    CP_WAIT0();
    __syncthreads();

    // pipelined mainloop
    for (int jt = 0; jt < NT; jt++) {
        const int p = jt & 1, q = p ^ 1;

        agen(p, maC, mbC);
        __syncthreads();

        uint32_t maN = 0, mbN = 0;
        if (jt + 1 < NT) {
            stage(jt + 1, q);
            maN = __ldg(mba + jt + 1);
            mbN = __ldg(mbb + jt + 1);
        }

        consume(p);

        if (jt + 1 < NT) CP_WAIT0();
        __syncthreads();
        maC = maN; mbC = mbN;
    }

    // epilogue: accumulators are final pre-ReLU outputs
#pragma unroll
    for (int mt = 0; mt < 2; mt++) {
        const int row = i0 + mw * 32 + mt * 16 + r;
#pragma unroll
        for (int nt = 0; nt < 4; nt++) {
            const int col = nw * 32 + nt * 8 + c * 2;
            float* op = out + ((size_t)(b * NN + row)) * FOUT + col;
            *(float2*)op = make_float2(fmaxf(acc[mt][nt][0], 0.f),
                                       fmaxf(acc[mt][nt][1], 0.f));
            *(float2*)(op + 8 * FOUT) = make_float2(fmaxf(acc[mt][nt][2], 0.f),
                                                    fmaxf(acc[mt][nt][3], 0.f));
        }
    }
}

// ---------------------------------------------------------------------------
extern "C" void kernel_launch(void* const* d_in, const int* in_sizes, int n_in,
                              void* d_out, int out_size)
{
    const float* h      = (const float*)d_in[0];
    const int*   adj    = (const int*)d_in[1];
    const float* W_w    = (const float*)d_in[2];
    const float* W_b    = (const float*)d_in[3];
    const float* attn_w = (const float*)d_in[4];
    float* out = (float*)d_out;

    adjbits_kernel<<<NN, 64>>>(adj);
    wh2_kernel<<<(Bb * NN) / 32, 256>>>(h, W_w, W_b);
    pack_kernel<<<(Bb * NN) / 8, 256>>>(attn_w);
    bfrag_kernel<<<dim3(NT, Bb), 256>>>();
    zsum_kernel<<<dim3(NN / 32, Bb), 256>>>();

    cudaFuncSetAttribute(gat_main_mma,
                         cudaFuncAttributeMaxDynamicSharedMemorySize, SMEM_BYTES);
    gat_main_mma<<<dim3(NN / 64, Bb), 256, SMEM_BYTES>>>(out);
}